// round 6
// baseline (speedup 1.0000x reference)
#include <cuda_runtime.h>
#include <math.h>

#define B 2
#define S 2048
#define H 8
#define D 64
#define DM 512
#define PAD 65

// Scratch (allocation-free rule: __device__ globals)
__device__ float g_Q[B * H * S * D];   // 8 MB  [b,h,s,d]
__device__ float g_K[B * H * S * D];   // 8 MB
__device__ float g_V[B * H * S * D];   // 8 MB
__device__ float g_Ao[B * S * DM];     // 8 MB  [b,q, d*H+h]

// ---------------------------------------------------------------------------
// Kernel 1: fused per-head QKV projection.
// Rows r = (b*S+s)*H + h  index the input flat as X[r*64 + d]  (contiguous!).
// out[e] = sum_d X[r][d] * W[e][d] + bias[e], written to [b,h,s,e] layout.
// ---------------------------------------------------------------------------
__global__ void qkv_proj_kernel(const float* __restrict__ qin,
                                const float* __restrict__ kin,
                                const float* __restrict__ vin,
                                const float* __restrict__ Wq, const float* __restrict__ bq,
                                const float* __restrict__ Wk, const float* __restrict__ bk,
                                const float* __restrict__ Wv, const float* __restrict__ bv) {
    __shared__ float Xs[64][PAD];
    __shared__ float Ws[64][PAD];
    __shared__ float bsh[64];

    int which = blockIdx.y;
    const float* X; const float* W; const float* bias; float* out;
    if (which == 0)      { X = qin; W = Wq; bias = bq; out = g_Q; }
    else if (which == 1) { X = kin; W = Wk; bias = bk; out = g_K; }
    else                 { X = vin; W = Wv; bias = bv; out = g_V; }

    int row0 = blockIdx.x * 64;
    int tid = threadIdx.x;

    for (int i = tid; i < 64 * 64; i += 256) {
        int r = i >> 6, c = i & 63;
        Xs[r][c] = X[(size_t)(row0 + r) * 64 + c];
        Ws[r][c] = W[i];
    }
    if (tid < 64) bsh[tid] = bias[tid];
    __syncthreads();

    int tq = tid >> 4, tk = tid & 15;
    float acc[4][4] = {};
#pragma unroll 8
    for (int d = 0; d < 64; d++) {
        float xv[4], wv[4];
#pragma unroll
        for (int i = 0; i < 4; i++) xv[i] = Xs[tq * 4 + i][d];
#pragma unroll
        for (int j = 0; j < 4; j++) wv[j] = Ws[tk * 4 + j][d];
#pragma unroll
        for (int i = 0; i < 4; i++)
#pragma unroll
            for (int j = 0; j < 4; j++)
                acc[i][j] += xv[i] * wv[j];
    }

#pragma unroll
    for (int i = 0; i < 4; i++) {
        int r = row0 + tq * 4 + i;
        int h = r & (H - 1);          // H = 8
        int bsidx = r >> 3;           // b*S + s
        int b = bsidx >> 11;          // S = 2048
        int s = bsidx & (S - 1);
        float* o = out + (((size_t)(b * H + h)) * S + s) * D;
#pragma unroll
        for (int j = 0; j < 4; j++) {
            int e = tk * 4 + j;
            o[e] = acc[i][j] + bsh[e];
        }
    }
}

// ---------------------------------------------------------------------------
// Kernel 2: flash attention. One block = 64 query rows of one (b,h).
// Online softmax; m/l kept redundantly in registers of the 16-lane row group.
// ---------------------------------------------------------------------------
__global__ void attn_kernel(const int* __restrict__ mask) {
    extern __shared__ float sm[];
    float* Qs = sm;                    // [64][PAD]
    float* Ks = sm + 64 * PAD;
    float* Vs = sm + 2 * 64 * PAD;
    float* Ps = sm + 3 * 64 * PAD;
    float* mf = sm + 4 * 64 * PAD;     // [64] mask flags

    int qt = blockIdx.x & 31;          // S/64 = 32 q-tiles
    int bh = blockIdx.x >> 5;          // b*H + h
    int b = bh >> 3, h = bh & 7;
    int q0 = qt * 64;
    int tid = threadIdx.x;
    int tq = tid >> 4, tk = tid & 15;

    const float* Qg = g_Q + ((size_t)bh * S + q0) * D;
    const float* Kg = g_K + (size_t)bh * S * D;
    const float* Vg = g_V + (size_t)bh * S * D;
    const int* mg = mask + b * S;

    for (int i = tid; i < 64 * 64; i += 256) {
        int r = i >> 6, c = i & 63;
        Qs[r * PAD + c] = Qg[i];
    }

    float acc[4][4] = {};
    float mrow[4] = {-INFINITY, -INFINITY, -INFINITY, -INFINITY};
    float lrow[4] = {0.0f, 0.0f, 0.0f, 0.0f};

    for (int kt = 0; kt < S / 64; kt++) {
        __syncthreads();  // prev PV done (and first iter: Qs loaded)
        const float* kp = Kg + (size_t)kt * 64 * D;
        const float* vp = Vg + (size_t)kt * 64 * D;
        for (int i = tid; i < 64 * 64; i += 256) {
            int r = i >> 6, c = i & 63;
            Ks[r * PAD + c] = kp[i];
            Vs[r * PAD + c] = vp[i];
        }
        if (tid < 64) mf[tid] = (mg[kt * 64 + tid] != 0) ? 1.0f : 0.0f;
        __syncthreads();

        // scores: sc[i][j] = Q[q0+tq*4+i] . K[k0+tk*4+j]
        float sc[4][4] = {};
#pragma unroll 4
        for (int d = 0; d < 64; d++) {
            float qv[4], kv[4];
#pragma unroll
            for (int i = 0; i < 4; i++) qv[i] = Qs[(tq * 4 + i) * PAD + d];
#pragma unroll
            for (int j = 0; j < 4; j++) kv[j] = Ks[(tk * 4 + j) * PAD + d];
#pragma unroll
            for (int i = 0; i < 4; i++)
#pragma unroll
                for (int j = 0; j < 4; j++)
                    sc[i][j] += qv[i] * kv[j];
        }

        // scale (ref quirk: 2/H = 0.25) + mask (ref: -1e20 pre-scale = -2.5e19)
#pragma unroll
        for (int j = 0; j < 4; j++) {
            float flag = mf[tk * 4 + j];
#pragma unroll
            for (int i = 0; i < 4; i++)
                sc[i][j] = (flag != 0.0f) ? sc[i][j] * 0.25f : -2.5e19f;
        }

        // online softmax per row (16-lane group owns 4 rows; values identical
        // across the group after width-16 reductions -> no smem m/l needed)
#pragma unroll
        for (int i = 0; i < 4; i++) {
            float r = fmaxf(fmaxf(sc[i][0], sc[i][1]), fmaxf(sc[i][2], sc[i][3]));
#pragma unroll
            for (int o = 8; o >= 1; o >>= 1)
                r = fmaxf(r, __shfl_xor_sync(0xffffffffu, r, o, 16));
            float mnew = fmaxf(mrow[i], r);
            float psum = 0.0f;
#pragma unroll
            for (int j = 0; j < 4; j++) {
                float p = __expf(sc[i][j] - mnew);
                Ps[(tq * 4 + i) * PAD + tk * 4 + j] = p;
                psum += p;
            }
#pragma unroll
            for (int o = 8; o >= 1; o >>= 1)
                psum += __shfl_xor_sync(0xffffffffu, psum, o, 16);
            float corr = __expf(mrow[i] - mnew);
            mrow[i] = mnew;
            lrow[i] = lrow[i] * corr + psum;
#pragma unroll
            for (int j = 0; j < 4; j++) acc[i][j] *= corr;
        }
        __syncthreads();  // Ps visible

        // PV: acc[i][j] += sum_k P[q][k] * V[k][d]   (d = tk*4+j here)
#pragma unroll 4
        for (int k = 0; k < 64; k++) {
            float vv[4], pv[4];
#pragma unroll
            for (int j = 0; j < 4; j++) vv[j] = Vs[k * PAD + tk * 4 + j];
#pragma unroll
            for (int i = 0; i < 4; i++) pv[i] = Ps[(tq * 4 + i) * PAD + k];
#pragma unroll
            for (int i = 0; i < 4; i++)
#pragma unroll
                for (int j = 0; j < 4; j++)
                    acc[i][j] += pv[i] * vv[j];
        }
    }

    // write Ao[b, q, d*H + h]  (ref einsum gives (d,h) feature order)
#pragma unroll
    for (int i = 0; i < 4; i++) {
        float inv = 1.0f / lrow[i];
        int q = q0 + tq * 4 + i;
        float* o = g_Ao + ((size_t)(b * S + q)) * DM + h;
#pragma unroll
        for (int j = 0; j < 4; j++) {
            int d = tk * 4 + j;
            o[d * H] = acc[i][j] * inv;
        }
    }
}

// ---------------------------------------------------------------------------
// Kernel 3: output projection  Y = Ao @ Wo^T + bo   (4096 x 512 x 512)
// ---------------------------------------------------------------------------
__global__ void out_proj_kernel(const float* __restrict__ Wo,
                                const float* __restrict__ bo,
                                float* __restrict__ Y) {
    __shared__ float As[64][PAD];
    __shared__ float Ws[64][PAD];

    int row0 = blockIdx.x * 64;
    int col0 = blockIdx.y * 64;
    int tid = threadIdx.x;
    int tq = tid >> 4, tk = tid & 15;
    float acc[4][4] = {};

    for (int kc = 0; kc < DM / 64; kc++) {
        __syncthreads();
        for (int i = tid; i < 64 * 64; i += 256) {
            int r = i >> 6, c = i & 63;
            As[r][c] = g_Ao[(size_t)(row0 + r) * DM + kc * 64 + c];
            Ws[r][c] = Wo[(size_t)(col0 + r) * DM + kc * 64 + c];
        }
        __syncthreads();
#pragma unroll 4
        for (int d = 0; d < 64; d++) {
            float av[4], wv[4];
#pragma unroll
            for (int i = 0; i < 4; i++) av[i] = As[tq * 4 + i][d];
#pragma unroll
            for (int j = 0; j < 4; j++) wv[j] = Ws[tk * 4 + j][d];
#pragma unroll
            for (int i = 0; i < 4; i++)
#pragma unroll
                for (int j = 0; j < 4; j++)
                    acc[i][j] += av[i] * wv[j];
        }
    }

#pragma unroll
    for (int i = 0; i < 4; i++) {
        int r = row0 + tq * 4 + i;
#pragma unroll
        for (int j = 0; j < 4; j++) {
            int c = col0 + tk * 4 + j;
            Y[(size_t)r * DM + c] = acc[i][j] + bo[c];
        }
    }
}

// ---------------------------------------------------------------------------
extern "C" void kernel_launch(void* const* d_in, const int* in_sizes, int n_in,
                              void* d_out, int out_size) {
    const float* q  = (const float*)d_in[0];
    const float* k  = (const float*)d_in[1];
    const float* v  = (const float*)d_in[2];
    const float* Wq = (const float*)d_in[3];
    const float* bq = (const float*)d_in[4];
    const float* Wk = (const float*)d_in[5];
    const float* bk = (const float*)d_in[6];
    const float* Wv = (const float*)d_in[7];
    const float* bv = (const float*)d_in[8];
    const float* Wo = (const float*)d_in[9];
    const float* bo = (const float*)d_in[10];
    const int* mask = (const int*)d_in[11];
    float* out = (float*)d_out;

    // 1) QKV projections: 512 row-tiles x 3 matrices
    qkv_proj_kernel<<<dim3(B * S * H / 64, 3), 256>>>(q, k, v, Wq, bq, Wk, bk, Wv, bv);

    // 2) flash attention: B*H*(S/64) = 512 blocks, ~66.8 KB dynamic smem
    int smem_bytes = (4 * 64 * PAD + 64) * (int)sizeof(float);
    cudaFuncSetAttribute(attn_kernel, cudaFuncAttributeMaxDynamicSharedMemorySize,
                         smem_bytes);
    attn_kernel<<<B * H * (S / 64), 256, smem_bytes>>>(mask);

    // 3) output projection
    out_proj_kernel<<<dim3(B * S / 64, DM / 64), 256>>>(Wo, bo, out);
}

// round 10
// speedup vs baseline: 1.9192x; 1.9192x over previous
#include <cuda_runtime.h>
#include <math.h>

#define B 2
#define S 2048
#define H 8
#define D 64
#define DM 512
#define PAD 65      // scalar-kernel smem pad
#define KP 68       // K/V/P smem pad: (4n+d)%32 distinct for frag quads

// Scratch (allocation-free rule: __device__ globals)
__device__ float g_Q[B * H * S * D];   // [b,h,s,d]
__device__ float g_K[B * H * S * D];
__device__ float g_V[B * H * S * D];
__device__ float g_Ao[B * S * DM];     // [b,q, d*H+h]

__device__ __forceinline__ unsigned f2tf(float f) {
    unsigned u;
    asm("cvt.rna.tf32.f32 %0, %1;" : "=r"(u) : "f"(f));
    return u;
}

__device__ __forceinline__ void mma_tf32(float c[4], unsigned a0, unsigned a1,
                                         unsigned a2, unsigned a3,
                                         unsigned b0, unsigned b1) {
    asm volatile(
        "mma.sync.aligned.m16n8k8.row.col.f32.tf32.tf32.f32 "
        "{%0,%1,%2,%3}, {%4,%5,%6,%7}, {%8,%9}, {%0,%1,%2,%3};\n"
        : "+f"(c[0]), "+f"(c[1]), "+f"(c[2]), "+f"(c[3])
        : "r"(a0), "r"(a1), "r"(a2), "r"(a3), "r"(b0), "r"(b1));
}

// ---------------------------------------------------------------------------
// Kernel 1: fused per-head QKV projection (unchanged from baseline).
// ---------------------------------------------------------------------------
__global__ void qkv_proj_kernel(const float* __restrict__ qin,
                                const float* __restrict__ kin,
                                const float* __restrict__ vin,
                                const float* __restrict__ Wq, const float* __restrict__ bq,
                                const float* __restrict__ Wk, const float* __restrict__ bk,
                                const float* __restrict__ Wv, const float* __restrict__ bv) {
    __shared__ float Xs[64][PAD];
    __shared__ float Ws[64][PAD];
    __shared__ float bsh[64];

    int which = blockIdx.y;
    const float* X; const float* W; const float* bias; float* out;
    if (which == 0)      { X = qin; W = Wq; bias = bq; out = g_Q; }
    else if (which == 1) { X = kin; W = Wk; bias = bk; out = g_K; }
    else                 { X = vin; W = Wv; bias = bv; out = g_V; }

    int row0 = blockIdx.x * 64;
    int tid = threadIdx.x;

    for (int i = tid; i < 64 * 64; i += 256) {
        int r = i >> 6, c = i & 63;
        Xs[r][c] = X[(size_t)(row0 + r) * 64 + c];
        Ws[r][c] = W[i];
    }
    if (tid < 64) bsh[tid] = bias[tid];
    __syncthreads();

    int tq = tid >> 4, tk = tid & 15;
    float acc[4][4] = {};
#pragma unroll 8
    for (int d = 0; d < 64; d++) {
        float xv[4], wv[4];
#pragma unroll
        for (int i = 0; i < 4; i++) xv[i] = Xs[tq * 4 + i][d];
#pragma unroll
        for (int j = 0; j < 4; j++) wv[j] = Ws[tk * 4 + j][d];
#pragma unroll
        for (int i = 0; i < 4; i++)
#pragma unroll
            for (int j = 0; j < 4; j++)
                acc[i][j] += xv[i] * wv[j];
    }

#pragma unroll
    for (int i = 0; i < 4; i++) {
        int r = row0 + tq * 4 + i;
        int h = r & (H - 1);
        int bsidx = r >> 3;
        int b = bsidx >> 11;
        int s = bsidx & (S - 1);
        float* o = out + (((size_t)(b * H + h)) * S + s) * D;
#pragma unroll
        for (int j = 0; j < 4; j++) {
            int e = tk * 4 + j;
            o[e] = acc[i][j] + bsh[e];
        }
    }
}

// ---------------------------------------------------------------------------
// Kernel 2: flash attention with tf32 mma.sync.
// 1 CTA = 128 q rows of one (b,h); 8 warps x 16 rows; kv tile = 64.
// ---------------------------------------------------------------------------
__global__ void __launch_bounds__(256, 1) attn_kernel(const int* __restrict__ mask) {
    extern __shared__ float sm[];
    float* Ks = sm;                      // [64][KP]  (tf32-rounded)
    float* Vs = Ks + 64 * KP;            // [64][KP]  (tf32-rounded)
    float* Ps = Vs + 64 * KP;            // [128][KP] (tf32-rounded)
    float* mf = Ps + 128 * KP;           // [64]

    int qt = blockIdx.x & 15;            // S/128 = 16 q-tiles
    int bh = blockIdx.x >> 4;
    int b = bh >> 3, h = bh & 7;
    int q0 = qt * 128;
    int tid = threadIdx.x;
    int w = tid >> 5;                    // warp 0..7
    int lane = tid & 31;
    int gid = lane >> 2;                 // row group 0..7
    int t4 = lane & 3;                   // quad lane

    const float* Qg = g_Q + ((size_t)bh * S + q0) * D;
    const float* Kg = g_K + (size_t)bh * S * D;
    const float* Vg = g_V + (size_t)bh * S * D;
    const int* mg = mask + b * S;

    // Q as register-resident tf32 A-fragments: rows w*16+gid / +8
    unsigned qa[8][4];
    {
        int r0 = w * 16 + gid;
#pragma unroll
        for (int kt = 0; kt < 8; kt++) {
            int d0 = kt * 8 + t4;
            qa[kt][0] = f2tf(Qg[(size_t)r0 * D + d0]);
            qa[kt][1] = f2tf(Qg[(size_t)(r0 + 8) * D + d0]);
            qa[kt][2] = f2tf(Qg[(size_t)r0 * D + d0 + 4]);
            qa[kt][3] = f2tf(Qg[(size_t)(r0 + 8) * D + d0 + 4]);
        }
    }

    float o[8][4] = {};                  // 16x64 output accum per warp
    float m0 = -INFINITY, m1 = -INFINITY;
    float l0 = 0.0f, l1 = 0.0f;

    for (int kt_tile = 0; kt_tile < S / 64; kt_tile++) {
        const float* kp = Kg + (size_t)kt_tile * 64 * D;
        const float* vp = Vg + (size_t)kt_tile * 64 * D;
        for (int i = tid; i < 64 * 64; i += 256) {
            int r = i >> 6, c = i & 63;
            Ks[r * KP + c] = __uint_as_float(f2tf(kp[i]));
            Vs[r * KP + c] = __uint_as_float(f2tf(vp[i]));
        }
        if (tid < 64) mf[tid] = (mg[kt_tile * 64 + tid] != 0) ? 1.0f : 0.0f;
        __syncthreads();

        // ---- scores: S(16x64) = Q(16x64) . K^T ----
        float c[8][4] = {};
#pragma unroll
        for (int kt = 0; kt < 8; kt++) {
#pragma unroll
            for (int j = 0; j < 8; j++) {
                // B frag: B[d][n] = K[n][d], n = j*8+gid, d = kt*8+t4
                unsigned b0 = __float_as_uint(Ks[(j * 8 + gid) * KP + kt * 8 + t4]);
                unsigned b1 = __float_as_uint(Ks[(j * 8 + gid) * KP + kt * 8 + t4 + 4]);
                mma_tf32(c[j], qa[kt][0], qa[kt][1], qa[kt][2], qa[kt][3], b0, b1);
            }
        }

        // ---- scale + mask ----
#pragma unroll
        for (int j = 0; j < 8; j++) {
            float f0 = mf[j * 8 + 2 * t4];
            float f1 = mf[j * 8 + 2 * t4 + 1];
            c[j][0] = (f0 != 0.0f) ? c[j][0] * 0.25f : -2.5e19f;
            c[j][1] = (f1 != 0.0f) ? c[j][1] * 0.25f : -2.5e19f;
            c[j][2] = (f0 != 0.0f) ? c[j][2] * 0.25f : -2.5e19f;
            c[j][3] = (f1 != 0.0f) ? c[j][3] * 0.25f : -2.5e19f;
        }

        // ---- online softmax (row r0 = regs 0,1; row r1 = regs 2,3) ----
        float rm0 = -INFINITY, rm1 = -INFINITY;
#pragma unroll
        for (int j = 0; j < 8; j++) {
            rm0 = fmaxf(rm0, fmaxf(c[j][0], c[j][1]));
            rm1 = fmaxf(rm1, fmaxf(c[j][2], c[j][3]));
        }
        rm0 = fmaxf(rm0, __shfl_xor_sync(0xffffffffu, rm0, 1));
        rm0 = fmaxf(rm0, __shfl_xor_sync(0xffffffffu, rm0, 2));
        rm1 = fmaxf(rm1, __shfl_xor_sync(0xffffffffu, rm1, 1));
        rm1 = fmaxf(rm1, __shfl_xor_sync(0xffffffffu, rm1, 2));
        float mn0 = fmaxf(m0, rm0), mn1 = fmaxf(m1, rm1);
        float cr0 = __expf(m0 - mn0), cr1 = __expf(m1 - mn1);
        m0 = mn0; m1 = mn1;

        float s0 = 0.0f, s1 = 0.0f;
        int pr0 = (w * 16 + gid) * KP;
        int pr1 = (w * 16 + gid + 8) * KP;
#pragma unroll
        for (int j = 0; j < 8; j++) {
            int col0 = j * 8 + 2 * t4;
            float p0 = __uint_as_float(f2tf(__expf(c[j][0] - mn0)));
            float p1 = __uint_as_float(f2tf(__expf(c[j][1] - mn0)));
            float p2 = __uint_as_float(f2tf(__expf(c[j][2] - mn1)));
            float p3 = __uint_as_float(f2tf(__expf(c[j][3] - mn1)));
            Ps[pr0 + col0] = p0;  Ps[pr0 + col0 + 1] = p1;
            Ps[pr1 + col0] = p2;  Ps[pr1 + col0 + 1] = p3;
            s0 += p0 + p1;  s1 += p2 + p3;
        }
        s0 += __shfl_xor_sync(0xffffffffu, s0, 1);
        s0 += __shfl_xor_sync(0xffffffffu, s0, 2);
        s1 += __shfl_xor_sync(0xffffffffu, s1, 1);
        s1 += __shfl_xor_sync(0xffffffffu, s1, 2);
        l0 = l0 * cr0 + s0;
        l1 = l1 * cr1 + s1;
#pragma unroll
        for (int j = 0; j < 8; j++) {
            o[j][0] *= cr0;  o[j][1] *= cr0;
            o[j][2] *= cr1;  o[j][3] *= cr1;
        }
        __syncthreads();     // Ps visible

        // ---- PV: O(16x64) += P(16x64) . V(64x64) ----
#pragma unroll
        for (int kt = 0; kt < 8; kt++) {
            unsigned a0 = __float_as_uint(Ps[(w * 16 + gid) * KP + kt * 8 + t4]);
            unsigned a1 = __float_as_uint(Ps[(w * 16 + gid + 8) * KP + kt * 8 + t4]);
            unsigned a2 = __float_as_uint(Ps[(w * 16 + gid) * KP + kt * 8 + t4 + 4]);
            unsigned a3 = __float_as_uint(Ps[(w * 16 + gid + 8) * KP + kt * 8 + t4 + 4]);
#pragma unroll
            for (int j = 0; j < 8; j++) {
                // B frag: V[k][n], k = kt*8+t4, n = j*8+gid
                unsigned b0 = __float_as_uint(Vs[(kt * 8 + t4) * KP + j * 8 + gid]);
                unsigned b1 = __float_as_uint(Vs[(kt * 8 + t4 + 4) * KP + j * 8 + gid]);
                mma_tf32(o[j], a0, a1, a2, a3, b0, b1);
            }
        }
        __syncthreads();     // Vs/Ps safe to overwrite next iter
    }

    // ---- write Ao[b, q, d*H + h] ----
    float inv0 = 1.0f / l0, inv1 = 1.0f / l1;
    int qr0 = q0 + w * 16 + gid;
    float* ob0 = g_Ao + ((size_t)(b * S + qr0)) * DM + h;
    float* ob1 = g_Ao + ((size_t)(b * S + qr0 + 8)) * DM + h;
#pragma unroll
    for (int j = 0; j < 8; j++) {
        int d0 = j * 8 + 2 * t4;
        ob0[d0 * H] = o[j][0] * inv0;
        ob0[(d0 + 1) * H] = o[j][1] * inv0;
        ob1[d0 * H] = o[j][2] * inv1;
        ob1[(d0 + 1) * H] = o[j][3] * inv1;
    }
}

// ---------------------------------------------------------------------------
// Kernel 3: output projection  Y = Ao @ Wo^T + bo  (unchanged)
// ---------------------------------------------------------------------------
__global__ void out_proj_kernel(const float* __restrict__ Wo,
                                const float* __restrict__ bo,
                                float* __restrict__ Y) {
    __shared__ float As[64][PAD];
    __shared__ float Ws[64][PAD];

    int row0 = blockIdx.x * 64;
    int col0 = blockIdx.y * 64;
    int tid = threadIdx.x;
    int tq = tid >> 4, tk = tid & 15;
    float acc[4][4] = {};

    for (int kc = 0; kc < DM / 64; kc++) {
        __syncthreads();
        for (int i = tid; i < 64 * 64; i += 256) {
            int r = i >> 6, c = i & 63;
            As[r][c] = g_Ao[(size_t)(row0 + r) * DM + kc * 64 + c];
            Ws[r][c] = Wo[(size_t)(col0 + r) * DM + kc * 64 + c];
        }
        __syncthreads();
#pragma unroll 4
        for (int d = 0; d < 64; d++) {
            float av[4], wv[4];
#pragma unroll
            for (int i = 0; i < 4; i++) av[i] = As[tq * 4 + i][d];
#pragma unroll
            for (int j = 0; j < 4; j++) wv[j] = Ws[tk * 4 + j][d];
#pragma unroll
            for (int i = 0; i < 4; i++)
#pragma unroll
                for (int j = 0; j < 4; j++)
                    acc[i][j] += av[i] * wv[j];
        }
    }

#pragma unroll
    for (int i = 0; i < 4; i++) {
        int r = row0 + tq * 4 + i;
#pragma unroll
        for (int j = 0; j < 4; j++) {
            int c = col0 + tk * 4 + j;
            Y[(size_t)r * DM + c] = acc[i][j] + bo[c];
        }
    }
}

// ---------------------------------------------------------------------------
extern "C" void kernel_launch(void* const* d_in, const int* in_sizes, int n_in,
                              void* d_out, int out_size) {
    const float* q  = (const float*)d_in[0];
    const float* k  = (const float*)d_in[1];
    const float* v  = (const float*)d_in[2];
    const float* Wq = (const float*)d_in[3];
    const float* bq = (const float*)d_in[4];
    const float* Wk = (const float*)d_in[5];
    const float* bk = (const float*)d_in[6];
    const float* Wv = (const float*)d_in[7];
    const float* bv = (const float*)d_in[8];
    const float* Wo = (const float*)d_in[9];
    const float* bo = (const float*)d_in[10];
    const int* mask = (const int*)d_in[11];
    float* out = (float*)d_out;

    qkv_proj_kernel<<<dim3(B * S * H / 64, 3), 256>>>(q, k, v, Wq, bq, Wk, bk, Wv, bv);

    int smem_bytes = (64 * KP + 64 * KP + 128 * KP + 64) * (int)sizeof(float);
    cudaFuncSetAttribute(attn_kernel, cudaFuncAttributeMaxDynamicSharedMemorySize,
                         smem_bytes);
    attn_kernel<<<B * H * (S / 128), 256, smem_bytes>>>(mask);

    out_proj_kernel<<<dim3(B * S / 64, DM / 64), 256>>>(Wo, bo, out);
}

// round 11
// speedup vs baseline: 3.1037x; 1.6172x over previous
#include <cuda_runtime.h>
#include <math.h>
#include <stdint.h>

#define B 2
#define S 2048
#define H 8
#define D 64
#define DM 512
#define KP 72   // smem pad: both (8*gid+t4) and (8*t4+gid) frag patterns conflict-free

// Scratch (allocation-free rule: __device__ globals)
__device__ float g_Q[B * H * S * D];   // [b,h,s,d]
__device__ float g_K[B * H * S * D];
__device__ float g_V[B * H * S * D];
__device__ float g_Ao[B * S * DM];     // [b,q, d*H+h]

__device__ __forceinline__ unsigned f2tf(float f) {
    unsigned u;
    asm("cvt.rna.tf32.f32 %0, %1;" : "=r"(u) : "f"(f));
    return u;
}

__device__ __forceinline__ void mma_tf32(float c[4], unsigned a0, unsigned a1,
                                         unsigned a2, unsigned a3,
                                         unsigned b0, unsigned b1) {
    asm volatile(
        "mma.sync.aligned.m16n8k8.row.col.f32.tf32.tf32.f32 "
        "{%0,%1,%2,%3}, {%4,%5,%6,%7}, {%8,%9}, {%0,%1,%2,%3};\n"
        : "+f"(c[0]), "+f"(c[1]), "+f"(c[2]), "+f"(c[3])
        : "r"(a0), "r"(a1), "r"(a2), "r"(a3), "r"(b0), "r"(b1));
}

__device__ __forceinline__ uint32_t smem_u32(const void* p) {
    return (uint32_t)__cvta_generic_to_shared(p);
}
__device__ __forceinline__ void cp16(uint32_t dst, const void* src) {
    asm volatile("cp.async.cg.shared.global [%0], [%1], 16;" :: "r"(dst), "l"(src));
}
#define CP_COMMIT() asm volatile("cp.async.commit_group;")
#define CP_WAIT1()  asm volatile("cp.async.wait_group 1;")

// ---------------------------------------------------------------------------
// Kernel 1: fused per-head QKV projection via tf32 mma.
// 128 rows x 64 cols per block, K=64. Rows r=(b*S+s)*H+h index input flat.
// ---------------------------------------------------------------------------
__global__ void __launch_bounds__(256) qkv_proj_kernel(
        const float* __restrict__ qin, const float* __restrict__ kin,
        const float* __restrict__ vin,
        const float* __restrict__ Wq, const float* __restrict__ bq,
        const float* __restrict__ Wk, const float* __restrict__ bk,
        const float* __restrict__ Wv, const float* __restrict__ bv) {
    extern __shared__ float sm[];
    float* Xs = sm;              // [128*KP]
    float* Ws = Xs + 128 * KP;   // [64*KP]
    float* bsh = Ws + 64 * KP;   // [64]

    int which = blockIdx.y;
    const float* X; const float* W; const float* bias; float* out;
    if (which == 0)      { X = qin; W = Wq; bias = bq; out = g_Q; }
    else if (which == 1) { X = kin; W = Wk; bias = bk; out = g_K; }
    else                 { X = vin; W = Wv; bias = bv; out = g_V; }

    int row0 = blockIdx.x * 128;
    int tid = threadIdx.x;

    for (int i = tid; i < 2048; i += 256) {
        int r = i >> 4, c = (i & 15) << 2;
        *(float4*)(Xs + r * KP + c) = *(const float4*)(X + (size_t)(row0 + r) * 64 + c);
    }
    for (int i = tid; i < 1024; i += 256) {
        int r = i >> 4, c = (i & 15) << 2;
        *(float4*)(Ws + r * KP + c) = *(const float4*)(W + (size_t)r * 64 + c);
    }
    if (tid < 64) bsh[tid] = bias[tid];
    __syncthreads();

    int w = tid >> 5, lane = tid & 31;
    int gid = lane >> 2, t4 = lane & 3;
    int rowA = (w * 16 + gid) * KP;

    float o[8][4] = {};
#pragma unroll
    for (int k8 = 0; k8 < 8; k8++) {
        int d0 = k8 * 8 + t4;
        unsigned a0 = f2tf(Xs[rowA + d0]);
        unsigned a1 = f2tf(Xs[rowA + 8 * KP + d0]);
        unsigned a2 = f2tf(Xs[rowA + d0 + 4]);
        unsigned a3 = f2tf(Xs[rowA + 8 * KP + d0 + 4]);
#pragma unroll
        for (int j = 0; j < 8; j++) {
            unsigned b0 = f2tf(Ws[(j * 8 + gid) * KP + d0]);
            unsigned b1 = f2tf(Ws[(j * 8 + gid) * KP + d0 + 4]);
            mma_tf32(o[j], a0, a1, a2, a3, b0, b1);
        }
    }

    // epilogue: C-frag rows (gid, gid+8), cols 2t4,2t4+1 per j-block
#pragma unroll
    for (int half = 0; half < 2; half++) {
        int r = row0 + w * 16 + gid + half * 8;
        int h = r & (H - 1);
        int bsi = r >> 3;
        int bb = bsi >> 11;
        int ss = bsi & (S - 1);
        float* op = out + (((size_t)(bb * H + h)) * S + ss) * D;
#pragma unroll
        for (int j = 0; j < 8; j++) {
            int e = j * 8 + 2 * t4;
            float2 v;
            v.x = o[j][half * 2]     + bsh[e];
            v.y = o[j][half * 2 + 1] + bsh[e + 1];
            *(float2*)(op + e) = v;
        }
    }
}

// ---------------------------------------------------------------------------
// Kernel 2: flash attention, tf32 mma, cp.async double-buffered K/V,
// register-resident P via width-4 shuffle layout conversion.
// 1 CTA = 128 q rows of one (b,h); 8 warps x 16 rows; kv tile = 64; occ 2.
// ---------------------------------------------------------------------------
__global__ void __launch_bounds__(256, 2) attn_kernel(const int* __restrict__ mask) {
    extern __shared__ float sm[];
    float* Qs  = sm;                    // [128*KP] raw f32
    float* Ks0 = Qs + 128 * KP;         // [2][64*KP]
    float* Vs0 = Ks0 + 2 * 64 * KP;     // [2][64*KP]
    int*   mfs = (int*)(Vs0 + 2 * 64 * KP);  // [2][64]

    int qt = blockIdx.x & 15;           // S/128 = 16 q-tiles
    int bh = blockIdx.x >> 4;
    int b = bh >> 3, h = bh & 7;
    int q0 = qt * 128;
    int tid = threadIdx.x;
    int w = tid >> 5, lane = tid & 31;
    int gid = lane >> 2, t4 = lane & 3;
    int srcA = t4 >> 1, srcB = srcA + 2;
    bool odd = (t4 & 1) != 0;

    const float* Qg = g_Q + ((size_t)bh * S + q0) * D;
    const float* Kg = g_K + (size_t)bh * S * D;
    const float* Vg = g_V + (size_t)bh * S * D;
    const int* mg = mask + b * S;

    // group 0: Q + K/V tile 0 + mask 0
    for (int i = tid; i < 2048; i += 256) {
        int r = i >> 4, c = (i & 15) << 2;
        cp16(smem_u32(Qs + r * KP + c), Qg + (size_t)r * 64 + c);
    }
    for (int i = tid; i < 1024; i += 256) {
        int r = i >> 4, c = (i & 15) << 2;
        cp16(smem_u32(Ks0 + r * KP + c), Kg + (size_t)r * 64 + c);
        cp16(smem_u32(Vs0 + r * KP + c), Vg + (size_t)r * 64 + c);
    }
    if (tid < 16) cp16(smem_u32(mfs + tid * 4), mg + tid * 4);
    CP_COMMIT();

    float o[8][4] = {};
    float m0 = -INFINITY, m1 = -INFINITY;
    float l0 = 0.0f, l1 = 0.0f;
    int rowA = (w * 16 + gid) * KP;

    for (int kt = 0; kt < S / 64; kt++) {
        int buf = kt & 1;
        float* Ks = Ks0 + buf * 64 * KP;
        float* Vs = Vs0 + buf * 64 * KP;
        int* mf = mfs + buf * 64;

        // prefetch next tile into the other buffer
        if (kt + 1 < S / 64) {
            int nb = buf ^ 1;
            const float* kp = Kg + (size_t)(kt + 1) * 64 * D;
            const float* vp = Vg + (size_t)(kt + 1) * 64 * D;
            float* Kn = Ks0 + nb * 64 * KP;
            float* Vn = Vs0 + nb * 64 * KP;
            for (int i = tid; i < 1024; i += 256) {
                int r = i >> 4, c = (i & 15) << 2;
                cp16(smem_u32(Kn + r * KP + c), kp + (size_t)r * 64 + c);
                cp16(smem_u32(Vn + r * KP + c), vp + (size_t)r * 64 + c);
            }
            if (tid < 16) cp16(smem_u32(mfs + nb * 64 + tid * 4),
                               mg + (kt + 1) * 64 + tid * 4);
        }
        CP_COMMIT();
        CP_WAIT1();
        __syncthreads();   // tile kt visible to all threads

        // ---- QK^T: S(16x64) per warp ----
        float c[8][4] = {};
#pragma unroll
        for (int k8 = 0; k8 < 8; k8++) {
            int d0 = k8 * 8 + t4;
            unsigned a0 = f2tf(Qs[rowA + d0]);
            unsigned a1 = f2tf(Qs[rowA + 8 * KP + d0]);
            unsigned a2 = f2tf(Qs[rowA + d0 + 4]);
            unsigned a3 = f2tf(Qs[rowA + 8 * KP + d0 + 4]);
#pragma unroll
            for (int j = 0; j < 8; j++) {
                unsigned b0 = f2tf(Ks[(j * 8 + gid) * KP + d0]);
                unsigned b1 = f2tf(Ks[(j * 8 + gid) * KP + d0 + 4]);
                mma_tf32(c[j], a0, a1, a2, a3, b0, b1);
            }
        }

        // ---- C-layout -> A-layout (quad shuffles) + mask + scale ----
        // After this: c[j][0]=row gid col j*8+t4, c[j][1]=row gid+8 col j*8+t4,
        //             c[j][2]=row gid col +4,     c[j][3]=row gid+8 col +4.
#pragma unroll
        for (int j = 0; j < 8; j++) {
            float l00 = __shfl_sync(0xffffffffu, c[j][0], srcA, 4);
            float l01 = __shfl_sync(0xffffffffu, c[j][1], srcA, 4);
            float l20 = __shfl_sync(0xffffffffu, c[j][2], srcA, 4);
            float l21 = __shfl_sync(0xffffffffu, c[j][3], srcA, 4);
            float h00 = __shfl_sync(0xffffffffu, c[j][0], srcB, 4);
            float h01 = __shfl_sync(0xffffffffu, c[j][1], srcB, 4);
            float h20 = __shfl_sync(0xffffffffu, c[j][2], srcB, 4);
            float h21 = __shfl_sync(0xffffffffu, c[j][3], srcB, 4);
            float a0 = odd ? l01 : l00;
            float a1 = odd ? l21 : l20;
            float a2 = odd ? h01 : h00;
            float a3 = odd ? h21 : h20;
            bool f0 = mf[j * 8 + t4] != 0;
            bool f4 = mf[j * 8 + t4 + 4] != 0;
            c[j][0] = f0 ? a0 * 0.25f : -2.5e19f;
            c[j][1] = f0 ? a1 * 0.25f : -2.5e19f;
            c[j][2] = f4 ? a2 * 0.25f : -2.5e19f;
            c[j][3] = f4 ? a3 * 0.25f : -2.5e19f;
        }

        // ---- online softmax (row gid: regs 0,2; row gid+8: regs 1,3) ----
        float rm0 = -INFINITY, rm1 = -INFINITY;
#pragma unroll
        for (int j = 0; j < 8; j++) {
            rm0 = fmaxf(rm0, fmaxf(c[j][0], c[j][2]));
            rm1 = fmaxf(rm1, fmaxf(c[j][1], c[j][3]));
        }
        rm0 = fmaxf(rm0, __shfl_xor_sync(0xffffffffu, rm0, 1, 4));
        rm0 = fmaxf(rm0, __shfl_xor_sync(0xffffffffu, rm0, 2, 4));
        rm1 = fmaxf(rm1, __shfl_xor_sync(0xffffffffu, rm1, 1, 4));
        rm1 = fmaxf(rm1, __shfl_xor_sync(0xffffffffu, rm1, 2, 4));
        float mn0 = fmaxf(m0, rm0), mn1 = fmaxf(m1, rm1);
        float cr0 = __expf(m0 - mn0), cr1 = __expf(m1 - mn1);
        m0 = mn0; m1 = mn1;

        float s0 = 0.0f, s1 = 0.0f;
#pragma unroll
        for (int j = 0; j < 8; j++) {
            float p0 = __uint_as_float(f2tf(__expf(c[j][0] - mn0)));
            float p1 = __uint_as_float(f2tf(__expf(c[j][1] - mn1)));
            float p2 = __uint_as_float(f2tf(__expf(c[j][2] - mn0)));
            float p3 = __uint_as_float(f2tf(__expf(c[j][3] - mn1)));
            c[j][0] = p0; c[j][1] = p1; c[j][2] = p2; c[j][3] = p3;
            s0 += p0 + p2;
            s1 += p1 + p3;
        }
        s0 += __shfl_xor_sync(0xffffffffu, s0, 1, 4);
        s0 += __shfl_xor_sync(0xffffffffu, s0, 2, 4);
        s1 += __shfl_xor_sync(0xffffffffu, s1, 1, 4);
        s1 += __shfl_xor_sync(0xffffffffu, s1, 2, 4);
        l0 = l0 * cr0 + s0;
        l1 = l1 * cr1 + s1;
#pragma unroll
        for (int j = 0; j < 8; j++) {     // o is C-layout: 0,1 row gid; 2,3 row gid+8
            o[j][0] *= cr0;  o[j][1] *= cr0;
            o[j][2] *= cr1;  o[j][3] *= cr1;
        }

        // ---- PV: O += P.V, P A-frags straight from registers ----
#pragma unroll
        for (int k8 = 0; k8 < 8; k8++) {
            unsigned a0 = __float_as_uint(c[k8][0]);
            unsigned a1 = __float_as_uint(c[k8][1]);
            unsigned a2 = __float_as_uint(c[k8][2]);
            unsigned a3 = __float_as_uint(c[k8][3]);
#pragma unroll
            for (int j = 0; j < 8; j++) {
                unsigned b0 = f2tf(Vs[(k8 * 8 + t4) * KP + j * 8 + gid]);
                unsigned b1 = f2tf(Vs[(k8 * 8 + t4 + 4) * KP + j * 8 + gid]);
                mma_tf32(o[j], a0, a1, a2, a3, b0, b1);
            }
        }
        __syncthreads();   // all warps done with buf before next prefetch hits it
    }

    // ---- write Ao[b, q, d*H + h] ----
    float inv0 = 1.0f / l0, inv1 = 1.0f / l1;
    int qr0 = q0 + w * 16 + gid;
    float* ob0 = g_Ao + ((size_t)(b * S + qr0)) * DM + h;
    float* ob1 = g_Ao + ((size_t)(b * S + qr0 + 8)) * DM + h;
#pragma unroll
    for (int j = 0; j < 8; j++) {
        int d0 = j * 8 + 2 * t4;
        ob0[d0 * H]       = o[j][0] * inv0;
        ob0[(d0 + 1) * H] = o[j][1] * inv0;
        ob1[d0 * H]       = o[j][2] * inv1;
        ob1[(d0 + 1) * H] = o[j][3] * inv1;
    }
}

// ---------------------------------------------------------------------------
// Kernel 3: output projection  Y = Ao @ Wo^T + bo via tf32 mma.
// Block tile 128x64, K-chunks of 64 (8 iters).
// ---------------------------------------------------------------------------
__global__ void __launch_bounds__(256) out_proj_kernel(
        const float* __restrict__ Wo, const float* __restrict__ bo,
        float* __restrict__ Y) {
    extern __shared__ float sm[];
    float* As = sm;              // [128*KP]
    float* Bs = As + 128 * KP;   // [64*KP]

    int row0 = blockIdx.x * 128;
    int col0 = blockIdx.y * 64;
    int tid = threadIdx.x;
    int w = tid >> 5, lane = tid & 31;
    int gid = lane >> 2, t4 = lane & 3;
    int rowA = (w * 16 + gid) * KP;

    float o[8][4] = {};
    for (int kc = 0; kc < DM / 64; kc++) {
        __syncthreads();
        for (int i = tid; i < 2048; i += 256) {
            int r = i >> 4, c = (i & 15) << 2;
            *(float4*)(As + r * KP + c) =
                *(const float4*)(g_Ao + (size_t)(row0 + r) * DM + kc * 64 + c);
        }
        for (int i = tid; i < 1024; i += 256) {
            int r = i >> 4, c = (i & 15) << 2;
            *(float4*)(Bs + r * KP + c) =
                *(const float4*)(Wo + (size_t)(col0 + r) * DM + kc * 64 + c);
        }
        __syncthreads();
#pragma unroll
        for (int k8 = 0; k8 < 8; k8++) {
            int d0 = k8 * 8 + t4;
            unsigned a0 = f2tf(As[rowA + d0]);
            unsigned a1 = f2tf(As[rowA + 8 * KP + d0]);
            unsigned a2 = f2tf(As[rowA + d0 + 4]);
            unsigned a3 = f2tf(As[rowA + 8 * KP + d0 + 4]);
#pragma unroll
            for (int j = 0; j < 8; j++) {
                unsigned b0 = f2tf(Bs[(j * 8 + gid) * KP + d0]);
                unsigned b1 = f2tf(Bs[(j * 8 + gid) * KP + d0 + 4]);
                mma_tf32(o[j], a0, a1, a2, a3, b0, b1);
            }
        }
    }

#pragma unroll
    for (int half = 0; half < 2; half++) {
        int r = row0 + w * 16 + gid + half * 8;
#pragma unroll
        for (int j = 0; j < 8; j++) {
            int cidx = col0 + j * 8 + 2 * t4;
            float2 v;
            v.x = o[j][half * 2]     + bo[cidx];
            v.y = o[j][half * 2 + 1] + bo[cidx + 1];
            *(float2*)(Y + (size_t)r * DM + cidx) = v;
        }
    }
}

// ---------------------------------------------------------------------------
extern "C" void kernel_launch(void* const* d_in, const int* in_sizes, int n_in,
                              void* d_out, int out_size) {
    const float* q  = (const float*)d_in[0];
    const float* k  = (const float*)d_in[1];
    const float* v  = (const float*)d_in[2];
    const float* Wq = (const float*)d_in[3];
    const float* bq = (const float*)d_in[4];
    const float* Wk = (const float*)d_in[5];
    const float* bk = (const float*)d_in[6];
    const float* Wv = (const float*)d_in[7];
    const float* bv = (const float*)d_in[8];
    const float* Wo = (const float*)d_in[9];
    const float* bo = (const float*)d_in[10];
    const int* mask = (const int*)d_in[11];
    float* out = (float*)d_out;

    // 1) QKV projections: 256 row-tiles x 3 matrices
    int qkv_smem = (128 * KP + 64 * KP + 64) * (int)sizeof(float);
    cudaFuncSetAttribute(qkv_proj_kernel,
                         cudaFuncAttributeMaxDynamicSharedMemorySize, qkv_smem);
    qkv_proj_kernel<<<dim3(B * S * H / 128, 3), 256, qkv_smem>>>(
        q, k, v, Wq, bq, Wk, bk, Wv, bv);

    // 2) flash attention: 256 blocks, 2 CTAs/SM
    int attn_smem = (128 * KP + 4 * 64 * KP) * (int)sizeof(float) + 2 * 64 * (int)sizeof(int);
    cudaFuncSetAttribute(attn_kernel,
                         cudaFuncAttributeMaxDynamicSharedMemorySize, attn_smem);
    attn_kernel<<<B * H * (S / 128), 256, attn_smem>>>(mask);

    // 3) output projection: 32 x 8 blocks
    int op_smem = (128 * KP + 64 * KP) * (int)sizeof(float);
    cudaFuncSetAttribute(out_proj_kernel,
                         cudaFuncAttributeMaxDynamicSharedMemorySize, op_smem);
    out_proj_kernel<<<dim3(B * S / 128, DM / 64), 256, op_smem>>>(Wo, bo, out);
}